// round 12
// baseline (speedup 1.0000x reference)
#include <cuda_runtime.h>
#include <cstdint>

// CharRNN on GB300 (sm_103a), round 11: R10 + per-layer named barriers.
// 128 blocks x 640 threads. wids 10..19 = REC layers 0..9, wids 0..9 = GEMM.
// Tick sync is now LOCAL: bar(l+1) joins {GEMM_l, REC_l, GEMM_{l+1}} (96 thr,
// bar 10 = 64 thr). GEMM_l arrives bar(l+1) first (publish z_l), then bar(l)
// (consume h_{l-1}) -> release wave 10->1, no deadlock, layers drift by a
// constant phase offset (decorrelated LDS/FMA bursts, local skew absorption).
// Depth-8 rings + 4-step ticks keep reader (1 tick behind) on the opposite
// ring half from the writer: RAW and WAR both safe. Math identical to R9/R10.

#define NBLK  128
#define NTHR  640
#define ROWS  8
#define TT    1024
#define LL    10
#define HID   32
#define VOC   256
#define LST   36
#define RL    (ROWS*LST)
#define DEPTH 8
#define NTICK 275

typedef unsigned long long ull;

__device__ __forceinline__ void ffma2(ull &d, ull a, ull b) {
    asm("fma.rn.f32x2 %0, %1, %2, %0;" : "+l"(d) : "l"(a), "l"(b));
}
__device__ __forceinline__ float f2red(ull a) {
    float lo, hi;
    asm("mov.b64 {%0, %1}, %2;" : "=f"(lo), "=f"(hi) : "l"(a));
    return lo + hi;
}
__device__ __forceinline__ float tanh_fast(float x) {
    float e = __expf(2.0f * x);
    return 1.0f - __fdividef(2.0f, e + 1.0f);
}
__device__ __forceinline__ void nbar(int id, int cnt) {
    asm volatile("bar.sync %0, %1;" :: "r"(id), "r"(cnt) : "memory");
}

__global__ void __launch_bounds__(NTHR, 1)
charrnn_kernel(const int*   __restrict__ x,
               const float* __restrict__ emb,
               const float* __restrict__ W_ih,
               const float* __restrict__ W_hh,
               const float* __restrict__ b_ih,
               const float* __restrict__ b_hh,
               const float* __restrict__ W_fc,
               const float* __restrict__ b_fc,
               float*       __restrict__ out)
{
    extern __shared__ float smem[];
    float* sh  = smem;                        // h rings [LL][DEPTH][ROWS][LST]
    float* sz  = smem + LL * DEPTH * RL;      // z rings [LL][DEPTH][ROWS][LST]
    float* sxs = sz   + LL * DEPTH * RL;      // GEMM_0 stage [4][ROWS][LST]

    const int tid  = threadIdx.x;
    const int wid  = tid >> 5;
    const int lane = tid & 31;
    const int row0 = blockIdx.x * ROWS;

    for (int i = tid; i < LL * DEPTH * RL; i += NTHR) sh[i] = 0.0f;

    const bool isRec = (wid >= 10);
    const int  l     = isRec ? (wid - 10) : wid;

    float*       hown = sh + l * DEPTH * RL;
    const float* hup  = (l > 0) ? (sh + (l - 1) * DEPTH * RL) : sxs;
    float*       zl   = sz + l * DEPTH * RL;

    const int half = lane >> 4;
    const int rb   = half * 4;
    const int n0   = lane & 15;
    const int n1   = n0 + 16;

    // bar(l+1) member count: {GEMM_l, REC_l, GEMM_{l+1}} = 96, except l=9 -> 64
    const int barn_own = l + 1;                    // this layer's bar
    const int cnt_own  = (l == 9) ? 64 : 96;
    const int cnt_up   = 96;                       // bar(l) for l>=1 always 96

    if (isRec) {
        // ======================= REC warp: h = tanh(z + Whh.h) =======================
        ull whh0[16], whh1[16];
        {
            const ulonglong2* p = (const ulonglong2*)(W_hh + (l * HID + n0) * HID);
            #pragma unroll
            for (int q = 0; q < 8; ++q) { ulonglong2 v = p[q]; whh0[2*q] = v.x; whh0[2*q+1] = v.y; }
            p = (const ulonglong2*)(W_hh + (l * HID + n1) * HID);
            #pragma unroll
            for (int q = 0; q < 8; ++q) { ulonglong2 v = p[q]; whh1[2*q] = v.x; whh1[2*q+1] = v.y; }
        }
        __syncthreads();

        for (int v = 0; v < NTICK; ++v) {
            const int t0 = 4 * (v - 2 * l - 1);
            if (t0 >= 0 && t0 < TT) {
                #pragma unroll
                for (int st = 0; st < 4; ++st) {
                    const int t = t0 + st;
                    const float* hb   = hown + ((t - 1) & (DEPTH-1)) * RL;
                    const float* zrow = zl   + (t & (DEPTH-1)) * RL;
                    float*       ob   = hown + (t & (DEPTH-1)) * RL;

                    #pragma unroll
                    for (int g = 0; g < 2; ++g) {
                        const int rA = rb + 2*g;
                        const int rB = rA + 1;
                        ull a00 = 0ull, a01 = 0ull, a10 = 0ull, a11 = 0ull;
                        #pragma unroll
                        for (int q = 0; q < 8; ++q) {
                            ulonglong2 vA = *(const ulonglong2*)(hb + rA * LST + q * 4);
                            ulonglong2 vB = *(const ulonglong2*)(hb + rB * LST + q * 4);
                            ffma2(a00, whh0[2*q], vA.x); ffma2(a00, whh0[2*q+1], vA.y);
                            ffma2(a01, whh1[2*q], vA.x); ffma2(a01, whh1[2*q+1], vA.y);
                            ffma2(a10, whh0[2*q], vB.x); ffma2(a10, whh0[2*q+1], vB.y);
                            ffma2(a11, whh1[2*q], vB.x); ffma2(a11, whh1[2*q+1], vB.y);
                        }
                        ob[rA * LST + n0] = tanh_fast(f2red(a00) + zrow[rA * LST + n0]);
                        ob[rA * LST + n1] = tanh_fast(f2red(a01) + zrow[rA * LST + n1]);
                        ob[rB * LST + n0] = tanh_fast(f2red(a10) + zrow[rB * LST + n0]);
                        ob[rB * LST + n1] = tanh_fast(f2red(a11) + zrow[rB * LST + n1]);
                    }
                    __syncwarp();
                }
            }
            nbar(barn_own, cnt_own);   // rendezvous with GEMM_l (z) + GEMM_{l+1} (h)
        }
    } else {
        // ======================= GEMM warp: z = Wih.x + bias =======================
        ull wih0[16], wih1[16];
        {
            const ulonglong2* p = (const ulonglong2*)(W_ih + (l * HID + n0) * HID);
            #pragma unroll
            for (int q = 0; q < 8; ++q) { ulonglong2 v = p[q]; wih0[2*q] = v.x; wih0[2*q+1] = v.y; }
            p = (const ulonglong2*)(W_ih + (l * HID + n1) * HID);
            #pragma unroll
            for (int q = 0; q < 8; ++q) { ulonglong2 v = p[q]; wih1[2*q] = v.x; wih1[2*q+1] = v.y; }
        }
        const float bias0 = __ldg(&b_ih[l * HID + n0]) + __ldg(&b_hh[l * HID + n0]);
        const float bias1 = __ldg(&b_ih[l * HID + n1]) + __ldg(&b_hh[l * HID + n1]);
        __syncthreads();

        for (int v = 0; v < NTICK; ++v) {
            const int t0 = 4 * (v - 2 * l);
            if (t0 >= 0 && t0 < TT) {
                if (l == 0) {
                    #pragma unroll
                    for (int r = 0; r < ROWS; ++r) {
                        const int4 xi = *(const int4*)(x + (row0 + r) * TT + t0);
                        sxs[0 * RL + r * LST + lane] = __ldg(&emb[xi.x * HID + lane]);
                        sxs[1 * RL + r * LST + lane] = __ldg(&emb[xi.y * HID + lane]);
                        sxs[2 * RL + r * LST + lane] = __ldg(&emb[xi.z * HID + lane]);
                        sxs[3 * RL + r * LST + lane] = __ldg(&emb[xi.w * HID + lane]);
                    }
                    __syncwarp();
                }
                #pragma unroll
                for (int st = 0; st < 4; ++st) {
                    const int t = t0 + st;
                    const float* inb = (l == 0) ? (sxs + st * RL)
                                                : (hup + (t & (DEPTH-1)) * RL);
                    float* zo = zl + (t & (DEPTH-1)) * RL;

                    #pragma unroll
                    for (int g = 0; g < 2; ++g) {
                        const int rA = rb + 2*g;
                        const int rB = rA + 1;
                        ull a00 = 0ull, a01 = 0ull, a10 = 0ull, a11 = 0ull;
                        #pragma unroll
                        for (int q = 0; q < 8; ++q) {
                            ulonglong2 vA = *(const ulonglong2*)(inb + rA * LST + q * 4);
                            ulonglong2 vB = *(const ulonglong2*)(inb + rB * LST + q * 4);
                            ffma2(a00, wih0[2*q], vA.x); ffma2(a00, wih0[2*q+1], vA.y);
                            ffma2(a01, wih1[2*q], vA.x); ffma2(a01, wih1[2*q+1], vA.y);
                            ffma2(a10, wih0[2*q], vB.x); ffma2(a10, wih0[2*q+1], vB.y);
                            ffma2(a11, wih1[2*q], vB.x); ffma2(a11, wih1[2*q+1], vB.y);
                        }
                        zo[rA * LST + n0] = f2red(a00) + bias0;
                        zo[rA * LST + n1] = f2red(a01) + bias1;
                        zo[rB * LST + n0] = f2red(a10) + bias0;
                        zo[rB * LST + n1] = f2red(a11) + bias1;
                    }
                }
            }
            nbar(barn_own, cnt_own);            // publish z_l to REC_l
            if (l >= 1) nbar(l, cnt_up);        // consume h_{l-1} from REC_{l-1}
        }
    }

    __syncthreads();

    // ---- final FC: out = h9(1023) @ W_fc^T + b_fc ; slot 1023&7 = 7 ----
    const float* h9 = sh + ((LL - 1) * DEPTH + 7) * RL;
    for (int i = tid; i < ROWS * VOC; i += NTHR) {
        const int r  = i >> 8;
        const int vv = i & (VOC - 1);
        const float4* wfc = (const float4*)(W_fc + vv * HID);
        const float*  hr  = h9 + r * LST;
        float sum = __ldg(&b_fc[vv]);
        #pragma unroll
        for (int q = 0; q < 8; ++q) {
            float4 aw = wfc[q];
            sum += aw.x * hr[q*4+0] + aw.y * hr[q*4+1] + aw.z * hr[q*4+2] + aw.w * hr[q*4+3];
        }
        out[(row0 + r) * VOC + vv] = sum;
    }
}

extern "C" void kernel_launch(void* const* d_in, const int* in_sizes, int n_in,
                              void* d_out, int out_size)
{
    const int*   x    = (const int*)  d_in[0];
    const float* emb  = (const float*)d_in[1];
    const float* W_ih = (const float*)d_in[2];
    const float* W_hh = (const float*)d_in[3];
    const float* b_ih = (const float*)d_in[4];
    const float* b_hh = (const float*)d_in[5];
    const float* W_fc = (const float*)d_in[6];
    const float* b_fc = (const float*)d_in[7];
    float* out = (float*)d_out;

    const int shbytes = (2 * LL * DEPTH + 4) * RL * (int)sizeof(float);  // 188928
    cudaFuncSetAttribute(charrnn_kernel,
                         cudaFuncAttributeMaxDynamicSharedMemorySize, shbytes);
    charrnn_kernel<<<NBLK, NTHR, shbytes>>>(x, emb, W_ih, W_hh, b_ih, b_hh,
                                            W_fc, b_fc, out);
}

// round 13
// speedup vs baseline: 1.0140x; 1.0140x over previous
#include <cuda_runtime.h>
#include <cstdint>

// CharRNN on GB300 (sm_103a), round 12 = R9 (best) + GEMM_0 x-index prefetch.
// 128 blocks x 640 threads. wids 0..9 = REC layers, 10..19 = GEMM layers.
// Both roles: lane owns neurons (n, n+16) for its 4-row half; 4 steps/tick;
// depth-8 h/z rings; ONE __syncthreads per tick.
// NEW: GEMM_0 prefetches next tick's x int4 indices into registers (lane r
// holds row r's indices, shfl-distributed at use) so the cold DRAM x load
// has a full tick to land; only L1-hot emb gathers remain at tick start.

#define NBLK  128
#define NTHR  640
#define ROWS  8
#define TT    1024
#define LL    10
#define HID   32
#define VOC   256
#define LST   36
#define RL    (ROWS*LST)
#define DEPTH 8
#define NTICK 275

typedef unsigned long long ull;

__device__ __forceinline__ void ffma2(ull &d, ull a, ull b) {
    asm("fma.rn.f32x2 %0, %1, %2, %0;" : "+l"(d) : "l"(a), "l"(b));
}
__device__ __forceinline__ float f2red(ull a) {
    float lo, hi;
    asm("mov.b64 {%0, %1}, %2;" : "=f"(lo), "=f"(hi) : "l"(a));
    return lo + hi;
}
__device__ __forceinline__ float tanh_fast(float x) {
    float e = __expf(2.0f * x);
    return 1.0f - __fdividef(2.0f, e + 1.0f);
}

__global__ void __launch_bounds__(NTHR, 1)
charrnn_kernel(const int*   __restrict__ x,
               const float* __restrict__ emb,
               const float* __restrict__ W_ih,
               const float* __restrict__ W_hh,
               const float* __restrict__ b_ih,
               const float* __restrict__ b_hh,
               const float* __restrict__ W_fc,
               const float* __restrict__ b_fc,
               float*       __restrict__ out)
{
    extern __shared__ float smem[];
    float* sh  = smem;                        // h rings [LL][DEPTH][ROWS][LST]
    float* sz  = smem + LL * DEPTH * RL;      // z rings [LL][DEPTH][ROWS][LST]
    float* sxs = sz   + LL * DEPTH * RL;      // GEMM_0 stage [4][ROWS][LST]

    const int tid  = threadIdx.x;
    const int wid  = tid >> 5;
    const int lane = tid & 31;
    const int row0 = blockIdx.x * ROWS;

    for (int i = tid; i < LL * DEPTH * RL; i += NTHR) sh[i] = 0.0f;

    const bool isRec = (wid < 10);
    const int  l     = isRec ? wid : (wid - 10);

    float*       hown = sh + l * DEPTH * RL;
    const float* hup  = (l > 0) ? (sh + (l - 1) * DEPTH * RL) : sxs;
    float*       zl   = sz + l * DEPTH * RL;

    const int half = lane >> 4;       // row half (0: rows 0-3, 1: rows 4-7)
    const int rb   = half * 4;
    const int n0   = lane & 15;       // owned neurons n0, n0+16
    const int n1   = n0 + 16;

    if (isRec) {
        // ======================= REC warp: h = tanh(z + Whh.h) =======================
        ull whh0[16], whh1[16];
        {
            const ulonglong2* p = (const ulonglong2*)(W_hh + (l * HID + n0) * HID);
            #pragma unroll
            for (int q = 0; q < 8; ++q) { ulonglong2 v = p[q]; whh0[2*q] = v.x; whh0[2*q+1] = v.y; }
            p = (const ulonglong2*)(W_hh + (l * HID + n1) * HID);
            #pragma unroll
            for (int q = 0; q < 8; ++q) { ulonglong2 v = p[q]; whh1[2*q] = v.x; whh1[2*q+1] = v.y; }
        }
        __syncthreads();

        for (int v = 0; v < NTICK; ++v) {
            const int t0 = 4 * (v - 2 * l - 1);
            if (t0 >= 0 && t0 < TT) {
                #pragma unroll
                for (int st = 0; st < 4; ++st) {
                    const int t = t0 + st;
                    const float* hb   = hown + ((t - 1) & (DEPTH-1)) * RL;
                    const float* zrow = zl   + (t & (DEPTH-1)) * RL;
                    float*       ob   = hown + (t & (DEPTH-1)) * RL;

                    #pragma unroll
                    for (int g = 0; g < 2; ++g) {
                        const int rA = rb + 2*g;
                        const int rB = rA + 1;
                        ull a00 = 0ull, a01 = 0ull, a10 = 0ull, a11 = 0ull;
                        #pragma unroll
                        for (int q = 0; q < 8; ++q) {
                            ulonglong2 vA = *(const ulonglong2*)(hb + rA * LST + q * 4);
                            ulonglong2 vB = *(const ulonglong2*)(hb + rB * LST + q * 4);
                            ffma2(a00, whh0[2*q], vA.x); ffma2(a00, whh0[2*q+1], vA.y);
                            ffma2(a01, whh1[2*q], vA.x); ffma2(a01, whh1[2*q+1], vA.y);
                            ffma2(a10, whh0[2*q], vB.x); ffma2(a10, whh0[2*q+1], vB.y);
                            ffma2(a11, whh1[2*q], vB.x); ffma2(a11, whh1[2*q+1], vB.y);
                        }
                        ob[rA * LST + n0] = tanh_fast(f2red(a00) + zrow[rA * LST + n0]);
                        ob[rA * LST + n1] = tanh_fast(f2red(a01) + zrow[rA * LST + n1]);
                        ob[rB * LST + n0] = tanh_fast(f2red(a10) + zrow[rB * LST + n0]);
                        ob[rB * LST + n1] = tanh_fast(f2red(a11) + zrow[rB * LST + n1]);
                    }
                    __syncwarp();
                }
            }
            __syncthreads();
        }
    } else {
        // ======================= GEMM warp: z = Wih.x + bias =======================
        ull wih0[16], wih1[16];
        {
            const ulonglong2* p = (const ulonglong2*)(W_ih + (l * HID + n0) * HID);
            #pragma unroll
            for (int q = 0; q < 8; ++q) { ulonglong2 v = p[q]; wih0[2*q] = v.x; wih0[2*q+1] = v.y; }
            p = (const ulonglong2*)(W_ih + (l * HID + n1) * HID);
            #pragma unroll
            for (int q = 0; q < 8; ++q) { ulonglong2 v = p[q]; wih1[2*q] = v.x; wih1[2*q+1] = v.y; }
        }
        const float bias0 = __ldg(&b_ih[l * HID + n0]) + __ldg(&b_hh[l * HID + n0]);
        const float bias1 = __ldg(&b_ih[l * HID + n1]) + __ldg(&b_hh[l * HID + n1]);

        // GEMM_0: prefetch x indices for its FIRST tick (t = 0..3).
        // Lane r (r < 8) holds row r's int4; distributed via shfl at use time.
        int4 xi = make_int4(0, 0, 0, 0);
        if (l == 0 && lane < ROWS)
            xi = *(const int4*)(x + (row0 + lane) * TT);

        __syncthreads();

        for (int v = 0; v < NTICK; ++v) {
            const int t0 = 4 * (v - 2 * l);
            if (t0 >= 0 && t0 < TT) {
                if (l == 0) {
                    // use prefetched indices (loaded one tick ago; DRAM latency hidden)
                    #pragma unroll
                    for (int r = 0; r < ROWS; ++r) {
                        const int ix = __shfl_sync(0xffffffffu, xi.x, r);
                        const int iy = __shfl_sync(0xffffffffu, xi.y, r);
                        const int iz = __shfl_sync(0xffffffffu, xi.z, r);
                        const int iw = __shfl_sync(0xffffffffu, xi.w, r);
                        sxs[0 * RL + r * LST + lane] = __ldg(&emb[ix * HID + lane]);
                        sxs[1 * RL + r * LST + lane] = __ldg(&emb[iy * HID + lane]);
                        sxs[2 * RL + r * LST + lane] = __ldg(&emb[iz * HID + lane]);
                        sxs[3 * RL + r * LST + lane] = __ldg(&emb[iw * HID + lane]);
                    }
                    // prefetch next tick's indices (full tick of slack to land)
                    if (lane < ROWS && t0 + 4 < TT)
                        xi = *(const int4*)(x + (row0 + lane) * TT + t0 + 4);
                    __syncwarp();
                }
                #pragma unroll
                for (int st = 0; st < 4; ++st) {
                    const int t = t0 + st;
                    const float* inb = (l == 0) ? (sxs + st * RL)
                                                : (hup + (t & (DEPTH-1)) * RL);
                    float* zo = zl + (t & (DEPTH-1)) * RL;

                    #pragma unroll
                    for (int g = 0; g < 2; ++g) {
                        const int rA = rb + 2*g;
                        const int rB = rA + 1;
                        ull a00 = 0ull, a01 = 0ull, a10 = 0ull, a11 = 0ull;
                        #pragma unroll
                        for (int q = 0; q < 8; ++q) {
                            ulonglong2 vA = *(const ulonglong2*)(inb + rA * LST + q * 4);
                            ulonglong2 vB = *(const ulonglong2*)(inb + rB * LST + q * 4);
                            ffma2(a00, wih0[2*q], vA.x); ffma2(a00, wih0[2*q+1], vA.y);
                            ffma2(a01, wih1[2*q], vA.x); ffma2(a01, wih1[2*q+1], vA.y);
                            ffma2(a10, wih0[2*q], vB.x); ffma2(a10, wih0[2*q+1], vB.y);
                            ffma2(a11, wih1[2*q], vB.x); ffma2(a11, wih1[2*q+1], vB.y);
                        }
                        zo[rA * LST + n0] = f2red(a00) + bias0;
                        zo[rA * LST + n1] = f2red(a01) + bias1;
                        zo[rB * LST + n0] = f2red(a10) + bias0;
                        zo[rB * LST + n1] = f2red(a11) + bias1;
                    }
                }
            }
            __syncthreads();
        }
    }

    __syncthreads();

    // ---- final FC: out = h9(1023) @ W_fc^T + b_fc ; slot 1023&7 = 7 ----
    const float* h9 = sh + ((LL - 1) * DEPTH + 7) * RL;
    for (int i = tid; i < ROWS * VOC; i += NTHR) {
        const int r  = i >> 8;
        const int vv = i & (VOC - 1);
        const float4* wfc = (const float4*)(W_fc + vv * HID);
        const float*  hr  = h9 + r * LST;
        float sum = __ldg(&b_fc[vv]);
        #pragma unroll
        for (int q = 0; q < 8; ++q) {
            float4 aw = wfc[q];
            sum += aw.x * hr[q*4+0] + aw.y * hr[q*4+1] + aw.z * hr[q*4+2] + aw.w * hr[q*4+3];
        }
        out[(row0 + r) * VOC + vv] = sum;
    }
}

extern "C" void kernel_launch(void* const* d_in, const int* in_sizes, int n_in,
                              void* d_out, int out_size)
{
    const int*   x    = (const int*)  d_in[0];
    const float* emb  = (const float*)d_in[1];
    const float* W_ih = (const float*)d_in[2];
    const float* W_hh = (const float*)d_in[3];
    const float* b_ih = (const float*)d_in[4];
    const float* b_hh = (const float*)d_in[5];
    const float* W_fc = (const float*)d_in[6];
    const float* b_fc = (const float*)d_in[7];
    float* out = (float*)d_out;

    const int shbytes = (2 * LL * DEPTH + 4) * RL * (int)sizeof(float);  // 188928
    cudaFuncSetAttribute(charrnn_kernel,
                         cudaFuncAttributeMaxDynamicSharedMemorySize, shbytes);
    charrnn_kernel<<<NBLK, NTHR, shbytes>>>(x, emb, W_ih, W_hh, b_ih, b_hh,
                                            W_fc, b_fc, out);
}